// round 8
// baseline (speedup 1.0000x reference)
#include <cuda_runtime.h>
#include <cuda_bf16.h>
#include <math.h>

// Problem constants (GraphAttentionLayer_85572928406097)
#define N_NODES   50000
#define N_EDGES   800000
#define IN_FEATS  128
#define OUT_FEATS 64
#define ALPHA     0.2f

// ---------------------------------------------------------------------------
// Scratch (__device__ globals; 16B-aligned)
// ---------------------------------------------------------------------------
__device__ __align__(16) float g_Wh[(size_t)N_NODES * OUT_FEATS];  // 12.8 MB
__device__ __align__(16) float g_s1[N_NODES];
__device__ __align__(16) float g_s2[N_NODES];
__device__ __align__(16) float g_exp[N_EDGES];                     // edge order
__device__ __align__(16) int   g_cnt[N_NODES];                     // in-degree
__device__ __align__(16) int   g_off[N_NODES + 1];                 // CSR offsets
__device__ __align__(16) int   g_cur[N_NODES];                     // cursors
__device__ __align__(16) int   g_csrc[N_EDGES];                    // CSR src
__device__ __align__(16) float g_cexp[N_EDGES];                    // CSR exp(e)
__device__ int g_is64;                                             // edge dtype flag

// ---------------------------------------------------------------------------
// K_detect: decide whether edge_index is int64 (little-endian) or int32.
// For int64 values < 2^31, every odd 32-bit word is 0. For int32 data, the
// odd words are random node ids (P(all 1024 == 0) ~ 0). Probes stay within
// the first 2048 words (< 2E words = in bounds for both layouts).
// ---------------------------------------------------------------------------
__global__ void k_detect(const int* __restrict__ ei) {
    __shared__ int any;
    if (threadIdx.x == 0) any = 0;
    __syncthreads();
    int v = ei[2 * threadIdx.x + 1];          // odd words 1,3,...,2047
    if (v != 0) atomicOr(&any, 1);
    __syncthreads();
    if (threadIdx.x == 0) g_is64 = (any == 0) ? 1 : 0;
}

// ---------------------------------------------------------------------------
// K0: zero the degree histogram
// ---------------------------------------------------------------------------
__global__ void k_zero(int n_nodes) {
    int i = blockIdx.x * blockDim.x + threadIdx.x;
    if (i < n_nodes) g_cnt[i] = 0;
}

// ---------------------------------------------------------------------------
// K1: Wh = h @ W.   Tile 32 rows x 64 cols, K=128. 256 threads.
//     smem: h tile 16 KB + full W 32 KB = 48 KB.
// ---------------------------------------------------------------------------
#define BM 32
__global__ __launch_bounds__(256) void k_gemm(const float* __restrict__ h,
                                              const float* __restrict__ W,
                                              int n) {
    __shared__ float hs[BM][IN_FEATS];        // 32 x 128
    __shared__ float Ws[IN_FEATS][OUT_FEATS]; // 128 x 64

    const int tid  = threadIdx.x;
    const int row0 = blockIdx.x * BM;

    // Load W (32 KB, contiguous) via float4
    {
        const float4* W4  = (const float4*)W;
        float4*       Ws4 = (float4*)&Ws[0][0];
        #pragma unroll
        for (int i = 0; i < 8; i++) Ws4[tid + i * 256] = W4[tid + i * 256];
    }
    // Load h tile (contiguous 16 KB), zero-pad past n
    {
        const float4* h4  = (const float4*)(h + (size_t)row0 * IN_FEATS);
        float4*       hs4 = (float4*)&hs[0][0];
        int nrow = n - row0; if (nrow > BM) nrow = BM;
        int nvec = nrow * (IN_FEATS / 4);
        #pragma unroll
        for (int i = 0; i < 4; i++) {
            int idx = tid + i * 256;
            float4 v = make_float4(0.f, 0.f, 0.f, 0.f);
            if (idx < nvec) v = h4[idx];
            hs4[idx] = v;
        }
    }
    __syncthreads();

    const int col  = tid & 63;   // 0..63
    const int rsub = tid >> 6;   // 0..3  (rows rsub + 4*r)

    float acc[8];
    #pragma unroll
    for (int r = 0; r < 8; r++) acc[r] = 0.0f;

    #pragma unroll
    for (int k = 0; k < IN_FEATS; k += 4) {
        const float w0 = Ws[k + 0][col];
        const float w1 = Ws[k + 1][col];
        const float w2 = Ws[k + 2][col];
        const float w3 = Ws[k + 3][col];
        #pragma unroll
        for (int r = 0; r < 8; r++) {
            const float4 hv = *(const float4*)&hs[rsub + r * 4][k]; // shared
            acc[r] = fmaf(hv.x, w0, acc[r]);
            acc[r] = fmaf(hv.y, w1, acc[r]);
            acc[r] = fmaf(hv.z, w2, acc[r]);
            acc[r] = fmaf(hv.w, w3, acc[r]);
        }
    }

    int nrow = n - row0; if (nrow > BM) nrow = BM;
    #pragma unroll
    for (int r = 0; r < 8; r++) {
        const int row = rsub + r * 4;
        if (row < nrow)
            g_Wh[(size_t)(row0 + row) * OUT_FEATS + col] = acc[r];
    }
}

// ---------------------------------------------------------------------------
// K2: s1[i] = Wh[i,:]·a1,  s2[i] = Wh[i,:]·a2.  One warp per node.
// ---------------------------------------------------------------------------
__global__ __launch_bounds__(256) void k_scores(const float* __restrict__ a, int n) {
    const int warp = (blockIdx.x * blockDim.x + threadIdx.x) >> 5;
    const int lane = threadIdx.x & 31;
    if (warp >= n) return;

    const float v0  = g_Wh[(size_t)warp * OUT_FEATS + lane];
    const float v1  = g_Wh[(size_t)warp * OUT_FEATS + 32 + lane];
    const float a10 = a[lane],             a11 = a[32 + lane];
    const float a20 = a[OUT_FEATS + lane], a21 = a[OUT_FEATS + 32 + lane];

    float p1 = v0 * a10 + v1 * a11;
    float p2 = v0 * a20 + v1 * a21;
    #pragma unroll
    for (int off = 16; off; off >>= 1) {
        p1 += __shfl_xor_sync(0xffffffffu, p1, off);
        p2 += __shfl_xor_sync(0xffffffffu, p2, off);
    }
    if (lane == 0) { g_s1[warp] = p1; g_s2[warp] = p2; }
}

// ---------------------------------------------------------------------------
// Edge fetch helper: layout-aware, clamped to [0, n) so no data surprise
// can produce an out-of-range access.
// ---------------------------------------------------------------------------
__device__ __forceinline__ void load_edge(const int* __restrict__ ei, int e,
                                          int ne, int n, int is64,
                                          int& src, int& dst) {
    if (is64) {            // int64 little-endian: low words at even indices
        src = ei[2 * e];
        dst = ei[2 * (ne + e)];
    } else {               // int32: [src(E), dst(E)]
        src = ei[e];
        dst = ei[ne + e];
    }
    if ((unsigned)src >= (unsigned)n) src = 0;
    if ((unsigned)dst >= (unsigned)n) dst = 0;
}

// ---------------------------------------------------------------------------
// K3: per-edge  exp(leaky_relu(s1[src]+s2[dst])) -> g_exp;  cnt[dst]++
// ---------------------------------------------------------------------------
__global__ __launch_bounds__(256) void k_edge(const int* __restrict__ ei,
                                              int ne, int n) {
    const int e = blockIdx.x * blockDim.x + threadIdx.x;
    if (e >= ne) return;
    const int is64 = g_is64;
    int src, dst;
    load_edge(ei, e, ne, n, is64, src, dst);
    const float s  = g_s1[src] + g_s2[dst];
    const float lr = s > 0.0f ? s : ALPHA * s;
    g_exp[e] = expf(lr);
    atomicAdd(g_cnt + dst, 1);
}

// ---------------------------------------------------------------------------
// K4: exclusive scan of g_cnt -> g_off (+ cursor copy).  One 256-thread block.
// ---------------------------------------------------------------------------
__global__ __launch_bounds__(256) void k_scan(int n) {
    const int T  = 256;
    const int t  = threadIdx.x;
    const int CH = (n + T - 1) / T;
    int beg = t * CH; if (beg > n) beg = n;
    int end = beg + CH; if (end > n) end = n;

    int sum = 0;
    for (int i = beg; i < end; i++) sum += g_cnt[i];

    __shared__ int ps[256];
    ps[t] = sum;
    __syncthreads();
    #pragma unroll
    for (int off = 1; off < 256; off <<= 1) {
        int v = (t >= off) ? ps[t - off] : 0;
        __syncthreads();
        ps[t] += v;
        __syncthreads();
    }
    int run = ps[t] - sum;   // exclusive prefix of this chunk

    for (int i = beg; i < end; i++) {
        int c = g_cnt[i];
        g_off[i] = run;
        g_cur[i] = run;
        run += c;
    }
    if (t == T - 1) g_off[n] = ps[T - 1];
}

// ---------------------------------------------------------------------------
// K5: fill CSR: slot = cur[dst]++;  csr_src[slot]=src; csr_exp[slot]=exp(e)
// ---------------------------------------------------------------------------
__global__ __launch_bounds__(256) void k_fill(const int* __restrict__ ei,
                                              int ne, int n) {
    const int e = blockIdx.x * blockDim.x + threadIdx.x;
    if (e >= ne) return;
    const int is64 = g_is64;
    int src, dst;
    load_edge(ei, e, ne, n, is64, src, dst);
    const int slot = atomicAdd(g_cur + dst, 1);
    g_csrc[slot] = src;
    g_cexp[slot] = g_exp[e];
}

// ---------------------------------------------------------------------------
// K6: gather per dst node (16 threads/node, one float4 feature slice/lane):
//     acc = sum_j exp_j * Wh[src_j, slice];  dsum = sum_j exp_j
//     out = elu(acc / dsum).  No atomics, fused normalize + ELU.
// ---------------------------------------------------------------------------
__global__ __launch_bounds__(256) void k_gather(float* __restrict__ out, int n) {
    const int gt   = blockIdx.x * blockDim.x + threadIdx.x;
    const int node = gt >> 4;
    const int lane = gt & 15;
    if (node >= n) return;

    const int beg = g_off[node];
    const int end = g_off[node + 1];

    const float4* __restrict__ Wh4 = (const float4*)g_Wh;
    float4 acc = make_float4(0.f, 0.f, 0.f, 0.f);
    float  dsum = 0.0f;

    for (int j = beg; j < end; j++) {
        const float w = g_cexp[j];     // broadcast across the 16 lanes
        const int   s = g_csrc[j];     // broadcast
        const float4 v = Wh4[(size_t)s * (OUT_FEATS / 4) + lane];
        acc.x = fmaf(w, v.x, acc.x);
        acc.y = fmaf(w, v.y, acc.y);
        acc.z = fmaf(w, v.z, acc.z);
        acc.w = fmaf(w, v.w, acc.w);
        dsum += w;
    }

    const float inv = (end > beg) ? (1.0f / dsum) : 0.0f;
    float4 r;
    r.x = acc.x * inv;  r.y = acc.y * inv;
    r.z = acc.z * inv;  r.w = acc.w * inv;
    r.x = r.x > 0.f ? r.x : expm1f(r.x);
    r.y = r.y > 0.f ? r.y : expm1f(r.y);
    r.z = r.z > 0.f ? r.z : expm1f(r.z);
    r.w = r.w > 0.f ? r.w : expm1f(r.w);

    ((float4*)out)[(size_t)node * (OUT_FEATS / 4) + lane] = r;
}

// ---------------------------------------------------------------------------
// Launcher.  Inputs identified by element count (robust to ordering):
//   h [N*128] f32 | edge_index (1.6M i32 / 1.6M i64 / 3.2M i32-view)
//   W [128*64] f32 | a [128] f32.      Output: [N*64] f32.
// ---------------------------------------------------------------------------
extern "C" void kernel_launch(void* const* d_in, const int* in_sizes, int n_in,
                              void* d_out, int out_size) {
    const float* h  = nullptr;
    const int*   ei = nullptr;
    const float* W  = nullptr;
    const float* a  = nullptr;
    int n = N_NODES, ne = N_EDGES;
    bool detect = true;

    for (int i = 0; i < n_in; i++) {
        const int sz = in_sizes[i];
        if (sz == IN_FEATS * OUT_FEATS)       W  = (const float*)d_in[i];
        else if (sz == 2 * OUT_FEATS)         a  = (const float*)d_in[i];
        else if (sz == 2 * N_EDGES)           { ei = (const int*)d_in[i]; ne = sz / 2; }
        else if (sz == 4 * N_EDGES)           { ei = (const int*)d_in[i]; ne = sz / 4;
                                                detect = true; /* i64 counted as i32 words;
                                                                  odd-word probe still decides */ }
        else                                  { h  = (const float*)d_in[i]; n = sz / IN_FEATS; }
    }
    if (n > N_NODES)  n  = N_NODES;   // protect static scratch
    if (ne > N_EDGES) ne = N_EDGES;

    k_detect<<<1, 1024>>>(ei);
    k_zero  <<<(n + 255) / 256, 256>>>(n);
    k_gemm  <<<(n + BM - 1) / BM, 256>>>(h, W, n);
    k_scores<<<(n * 32 + 255) / 256, 256>>>(a, n);
    k_edge  <<<(ne + 255) / 256, 256>>>(ei, ne, n);
    k_scan  <<<1, 256>>>(n);
    k_fill  <<<(ne + 255) / 256, 256>>>(ei, ne, n);
    k_gather<<<(n * 16 + 255) / 256, 256>>>((float*)d_out, n);
}

// round 10
// speedup vs baseline: 1.0557x; 1.0557x over previous
#include <cuda_runtime.h>
#include <cuda_bf16.h>
#include <math.h>

// Problem constants (GraphAttentionLayer_85572928406097)
#define N_NODES   50000
#define N_EDGES   800000
#define IN_FEATS  128
#define OUT_FEATS 64
#define ALPHA     0.2f

// ---------------------------------------------------------------------------
// Scratch (__device__ globals; 16B-aligned)
// ---------------------------------------------------------------------------
__device__ __align__(16) float g_Wh[(size_t)N_NODES * OUT_FEATS];  // 12.8 MB
__device__ __align__(16) float g_s1[N_NODES];
__device__ __align__(16) float g_s2[N_NODES];
__device__ __align__(16) int   g_cnt[N_NODES];                     // in-degree
__device__ __align__(16) int   g_off[N_NODES + 1];                 // CSR offsets
__device__ __align__(16) int   g_cur[N_NODES];                     // cursors
__device__ __align__(16) int   g_csrc[N_EDGES];                    // CSR src
__device__ __align__(16) float g_cexp[N_EDGES];                    // CSR exp(e)
__device__ int g_is64;                                             // edge dtype

// ---------------------------------------------------------------------------
// K_detect: int64 vs int32 edge_index (odd 32-bit words all zero <=> int64).
// ---------------------------------------------------------------------------
__global__ void k_detect(const int* __restrict__ ei) {
    __shared__ int any;
    if (threadIdx.x == 0) any = 0;
    __syncthreads();
    int v = ei[2 * threadIdx.x + 1];
    if (v != 0) atomicOr(&any, 1);
    __syncthreads();
    if (threadIdx.x == 0) g_is64 = (any == 0) ? 1 : 0;
}

// ---------------------------------------------------------------------------
// K0: zero the degree histogram
// ---------------------------------------------------------------------------
__global__ void k_zero(int n_nodes) {
    int i = blockIdx.x * blockDim.x + threadIdx.x;
    if (i < n_nodes) g_cnt[i] = 0;
}

// ---------------------------------------------------------------------------
// K1: Wh = h @ W  with fused score epilogue (s1 = Wh·a1, s2 = Wh·a2).
//     BM=32 rows x 64 cols, K=128.  128 threads; each owns 8 rows x 2 cols
//     (cols tx, tx+32) -> 2.5 B LDS per FMA (vs 4.5 before).
//     smem: h tile 16 KB + W 32 KB = 48 KB.
// ---------------------------------------------------------------------------
#define BM 32
__global__ __launch_bounds__(128) void k_gemm(const float* __restrict__ h,
                                              const float* __restrict__ W,
                                              const float* __restrict__ a,
                                              int n) {
    __shared__ float hs[BM][IN_FEATS];        // 32 x 128 = 16 KB
    __shared__ float Ws[IN_FEATS][OUT_FEATS]; // 128 x 64 = 32 KB

    const int tid  = threadIdx.x;
    const int row0 = blockIdx.x * BM;

    // Load W (2048 float4)
    {
        const float4* W4  = (const float4*)W;
        float4*       Ws4 = (float4*)&Ws[0][0];
        #pragma unroll
        for (int i = 0; i < 16; i++) Ws4[tid + i * 128] = W4[tid + i * 128];
    }
    // Load h tile (1024 float4), zero-pad past n
    {
        const float4* h4  = (const float4*)(h + (size_t)row0 * IN_FEATS);
        float4*       hs4 = (float4*)&hs[0][0];
        int nrow = n - row0; if (nrow > BM) nrow = BM;
        int nvec = nrow * (IN_FEATS / 4);
        #pragma unroll
        for (int i = 0; i < 8; i++) {
            int idx = tid + i * 128;
            float4 v = make_float4(0.f, 0.f, 0.f, 0.f);
            if (idx < nvec) v = h4[idx];
            hs4[idx] = v;
        }
    }
    __syncthreads();

    const int tx = tid & 31;   // lane: col pair {tx, tx+32}
    const int ty = tid >> 5;   // warp: rows ty + 4*r, r=0..7

    float acc0[8], acc1[8];
    #pragma unroll
    for (int r = 0; r < 8; r++) { acc0[r] = 0.f; acc1[r] = 0.f; }

    #pragma unroll
    for (int k = 0; k < IN_FEATS; k += 4) {
        const float w00 = Ws[k + 0][tx], w01 = Ws[k + 0][tx + 32];
        const float w10 = Ws[k + 1][tx], w11 = Ws[k + 1][tx + 32];
        const float w20 = Ws[k + 2][tx], w21 = Ws[k + 2][tx + 32];
        const float w30 = Ws[k + 3][tx], w31 = Ws[k + 3][tx + 32];
        #pragma unroll
        for (int r = 0; r < 8; r++) {
            const float4 hv = *(const float4*)&hs[ty + 4 * r][k]; // broadcast
            acc0[r] = fmaf(hv.x, w00, acc0[r]);
            acc0[r] = fmaf(hv.y, w10, acc0[r]);
            acc0[r] = fmaf(hv.z, w20, acc0[r]);
            acc0[r] = fmaf(hv.w, w30, acc0[r]);
            acc1[r] = fmaf(hv.x, w01, acc1[r]);
            acc1[r] = fmaf(hv.y, w11, acc1[r]);
            acc1[r] = fmaf(hv.z, w21, acc1[r]);
            acc1[r] = fmaf(hv.w, w31, acc1[r]);
        }
    }

    // Epilogue: store Wh rows + fused s1/s2 (warp reduce over 64 cols)
    const float a10 = a[tx], a11 = a[tx + 32];
    const float a20 = a[OUT_FEATS + tx], a21 = a[OUT_FEATS + tx + 32];

    int nrow = n - row0; if (nrow > BM) nrow = BM;
    #pragma unroll
    for (int r = 0; r < 8; r++) {
        const int row = ty + 4 * r;
        float p1 = acc0[r] * a10 + acc1[r] * a11;
        float p2 = acc0[r] * a20 + acc1[r] * a21;
        #pragma unroll
        for (int off = 16; off; off >>= 1) {
            p1 += __shfl_xor_sync(0xffffffffu, p1, off);
            p2 += __shfl_xor_sync(0xffffffffu, p2, off);
        }
        if (row < nrow) {
            float* dst = g_Wh + (size_t)(row0 + row) * OUT_FEATS;
            dst[tx]      = acc0[r];
            dst[tx + 32] = acc1[r];
            if (tx == 0) { g_s1[row0 + row] = p1; g_s2[row0 + row] = p2; }
        }
    }
}

// ---------------------------------------------------------------------------
// Edge fetch helper: layout-aware, clamped to [0, n).
// ---------------------------------------------------------------------------
__device__ __forceinline__ void load_edge(const int* __restrict__ ei, int e,
                                          int ne, int n, int is64,
                                          int& src, int& dst) {
    if (is64) { src = ei[2 * e]; dst = ei[2 * (ne + e)]; }
    else      { src = ei[e];     dst = ei[ne + e]; }
    if ((unsigned)src >= (unsigned)n) src = 0;
    if ((unsigned)dst >= (unsigned)n) dst = 0;
}

// ---------------------------------------------------------------------------
// K3: count-only in-degree histogram (dst word only)
// ---------------------------------------------------------------------------
__global__ __launch_bounds__(256) void k_edge(const int* __restrict__ ei,
                                              int ne, int n) {
    const int e = blockIdx.x * blockDim.x + threadIdx.x;
    if (e >= ne) return;
    int dst = g_is64 ? ei[2 * (ne + e)] : ei[ne + e];
    if ((unsigned)dst >= (unsigned)n) dst = 0;
    atomicAdd(g_cnt + dst, 1);
}

// ---------------------------------------------------------------------------
// K4: exclusive scan of g_cnt -> g_off (+ cursor copy).  One 1024-thr block.
// ---------------------------------------------------------------------------
__global__ __launch_bounds__(1024) void k_scan(int n) {
    const int T  = 1024;
    const int t  = threadIdx.x;
    const int CH = (n + T - 1) / T;
    int beg = t * CH; if (beg > n) beg = n;
    int end = beg + CH; if (end > n) end = n;

    int sum = 0;
    for (int i = beg; i < end; i++) sum += g_cnt[i];

    __shared__ int ps[1024];
    ps[t] = sum;
    __syncthreads();
    #pragma unroll
    for (int off = 1; off < 1024; off <<= 1) {
        int v = (t >= off) ? ps[t - off] : 0;
        __syncthreads();
        ps[t] += v;
        __syncthreads();
    }
    int run = ps[t] - sum;   // exclusive prefix of this chunk

    for (int i = beg; i < end; i++) {
        int c = g_cnt[i];
        g_off[i] = run;
        g_cur[i] = run;
        run += c;
    }
    if (t == T - 1) g_off[n] = ps[T - 1];
}

// ---------------------------------------------------------------------------
// K5: fill CSR with inline attention numerator:
//     slot = cur[dst]++;  csr_src[slot] = src;
//     csr_exp[slot] = exp(leaky_relu(s1[src] + s2[dst]))
// ---------------------------------------------------------------------------
__global__ __launch_bounds__(256) void k_fill(const int* __restrict__ ei,
                                              int ne, int n) {
    const int e = blockIdx.x * blockDim.x + threadIdx.x;
    if (e >= ne) return;
    const int is64 = g_is64;
    int src, dst;
    load_edge(ei, e, ne, n, is64, src, dst);
    const float s  = g_s1[src] + g_s2[dst];
    const float lr = s > 0.0f ? s : ALPHA * s;
    const int slot = atomicAdd(g_cur + dst, 1);
    g_csrc[slot] = src;
    g_cexp[slot] = expf(lr);
}

// ---------------------------------------------------------------------------
// K6: gather per dst node (16 threads/node, one float4 slice per lane):
//     acc = sum_j exp_j * Wh[src_j, slice];  dsum = sum_j exp_j
//     out = elu(acc / dsum).  No atomics; fused normalize + ELU.
// ---------------------------------------------------------------------------
__global__ __launch_bounds__(256) void k_gather(float* __restrict__ out, int n) {
    const int gt   = blockIdx.x * blockDim.x + threadIdx.x;
    const int node = gt >> 4;
    const int lane = gt & 15;
    if (node >= n) return;

    const int beg = g_off[node];
    const int end = g_off[node + 1];

    const float4* __restrict__ Wh4 = (const float4*)g_Wh;
    float4 acc = make_float4(0.f, 0.f, 0.f, 0.f);
    float  dsum = 0.0f;

    for (int j = beg; j < end; j++) {
        const float w = g_cexp[j];     // broadcast across the 16 lanes
        const int   s = g_csrc[j];     // broadcast
        const float4 v = Wh4[(size_t)s * (OUT_FEATS / 4) + lane];
        acc.x = fmaf(w, v.x, acc.x);
        acc.y = fmaf(w, v.y, acc.y);
        acc.z = fmaf(w, v.z, acc.z);
        acc.w = fmaf(w, v.w, acc.w);
        dsum += w;
    }

    const float inv = (end > beg) ? (1.0f / dsum) : 0.0f;
    float4 r;
    r.x = acc.x * inv;  r.y = acc.y * inv;
    r.z = acc.z * inv;  r.w = acc.w * inv;
    r.x = r.x > 0.f ? r.x : expm1f(r.x);
    r.y = r.y > 0.f ? r.y : expm1f(r.y);
    r.z = r.z > 0.f ? r.z : expm1f(r.z);
    r.w = r.w > 0.f ? r.w : expm1f(r.w);

    ((float4*)out)[(size_t)node * (OUT_FEATS / 4) + lane] = r;
}

// ---------------------------------------------------------------------------
// Launcher.  Inputs identified by element count (robust to ordering).
// ---------------------------------------------------------------------------
extern "C" void kernel_launch(void* const* d_in, const int* in_sizes, int n_in,
                              void* d_out, int out_size) {
    const float* h  = nullptr;
    const int*   ei = nullptr;
    const float* W  = nullptr;
    const float* a  = nullptr;
    int n = N_NODES, ne = N_EDGES;

    for (int i = 0; i < n_in; i++) {
        const int sz = in_sizes[i];
        if (sz == IN_FEATS * OUT_FEATS)       W  = (const float*)d_in[i];
        else if (sz == 2 * OUT_FEATS)         a  = (const float*)d_in[i];
        else if (sz == 2 * N_EDGES)           { ei = (const int*)d_in[i]; ne = sz / 2; }
        else if (sz == 4 * N_EDGES)           { ei = (const int*)d_in[i]; ne = sz / 4; }
        else                                  { h  = (const float*)d_in[i]; n = sz / IN_FEATS; }
    }
    if (n > N_NODES)  n  = N_NODES;   // protect static scratch
    if (ne > N_EDGES) ne = N_EDGES;

    k_detect<<<1, 1024>>>(ei);
    k_zero  <<<(n + 255) / 256, 256>>>(n);
    k_gemm  <<<(n + BM - 1) / BM, 128>>>(h, W, a, n);
    k_edge  <<<(ne + 255) / 256, 256>>>(ei, ne, n);
    k_scan  <<<1, 1024>>>(n);
    k_fill  <<<(ne + 255) / 256, 256>>>(ei, ne, n);
    k_gather<<<(n * 16 + 255) / 256, 256>>>((float*)d_out, n);
}

// round 11
// speedup vs baseline: 1.0956x; 1.0378x over previous
#include <cuda_runtime.h>
#include <cuda_bf16.h>
#include <math.h>

// Problem constants (GraphAttentionLayer_85572928406097)
#define N_NODES   50000
#define N_EDGES   800000
#define IN_FEATS  128
#define OUT_FEATS 64
#define ALPHA     0.2f

// ---------------------------------------------------------------------------
// Scratch (__device__ globals; 16B-aligned)
// ---------------------------------------------------------------------------
__device__ __align__(16) float g_Wh[(size_t)N_NODES * OUT_FEATS];  // 12.8 MB
__device__ __align__(16) float g_s1[N_NODES];
__device__ __align__(16) float g_s2[N_NODES];
__device__ __align__(16) int   g_cnt[N_NODES];                     // in-degree
__device__ __align__(16) int   g_off[N_NODES + 1];                 // CSR offsets
__device__ __align__(16) int   g_cur[N_NODES];                     // cursors
__device__ __align__(16) int2  g_cedge[N_EDGES];                   // {src, exp bits}
__device__ int g_is64;                                             // edge dtype

// ---------------------------------------------------------------------------
// K_init: zero histogram + dtype detect (block 0 probes 256 odd words;
// int64 values < 2^31 have all-zero odd words, int32 node ids do not).
// ---------------------------------------------------------------------------
__global__ void k_init(const int* __restrict__ ei, int n) {
    const int i = blockIdx.x * blockDim.x + threadIdx.x;
    if (i < n) g_cnt[i] = 0;
    if (blockIdx.x == 0) {
        __shared__ int any;
        if (threadIdx.x == 0) any = 0;
        __syncthreads();
        if (ei[2 * threadIdx.x + 1] != 0) atomicOr(&any, 1);
        __syncthreads();
        if (threadIdx.x == 0) g_is64 = (any == 0) ? 1 : 0;
    }
}

// ---------------------------------------------------------------------------
// K1: Wh = h @ W  with fused score epilogue (s1 = Wh·a1, s2 = Wh·a2).
//     BM=32 rows x 64 cols, K=128.  128 threads; each owns 8 rows x 2 cols.
// ---------------------------------------------------------------------------
#define BM 32
__global__ __launch_bounds__(128) void k_gemm(const float* __restrict__ h,
                                              const float* __restrict__ W,
                                              const float* __restrict__ a,
                                              int n) {
    __shared__ float hs[BM][IN_FEATS];        // 16 KB
    __shared__ float Ws[IN_FEATS][OUT_FEATS]; // 32 KB

    const int tid  = threadIdx.x;
    const int row0 = blockIdx.x * BM;

    {
        const float4* W4  = (const float4*)W;
        float4*       Ws4 = (float4*)&Ws[0][0];
        #pragma unroll
        for (int i = 0; i < 16; i++) Ws4[tid + i * 128] = W4[tid + i * 128];
    }
    {
        const float4* h4  = (const float4*)(h + (size_t)row0 * IN_FEATS);
        float4*       hs4 = (float4*)&hs[0][0];
        int nrow = n - row0; if (nrow > BM) nrow = BM;
        int nvec = nrow * (IN_FEATS / 4);
        #pragma unroll
        for (int i = 0; i < 8; i++) {
            int idx = tid + i * 128;
            float4 v = make_float4(0.f, 0.f, 0.f, 0.f);
            if (idx < nvec) v = h4[idx];
            hs4[idx] = v;
        }
    }
    __syncthreads();

    const int tx = tid & 31;   // lane: cols {tx, tx+32}
    const int ty = tid >> 5;   // warp: rows ty + 4*r

    float acc0[8], acc1[8];
    #pragma unroll
    for (int r = 0; r < 8; r++) { acc0[r] = 0.f; acc1[r] = 0.f; }

    #pragma unroll
    for (int k = 0; k < IN_FEATS; k += 4) {
        const float w00 = Ws[k + 0][tx], w01 = Ws[k + 0][tx + 32];
        const float w10 = Ws[k + 1][tx], w11 = Ws[k + 1][tx + 32];
        const float w20 = Ws[k + 2][tx], w21 = Ws[k + 2][tx + 32];
        const float w30 = Ws[k + 3][tx], w31 = Ws[k + 3][tx + 32];
        #pragma unroll
        for (int r = 0; r < 8; r++) {
            const float4 hv = *(const float4*)&hs[ty + 4 * r][k];
            acc0[r] = fmaf(hv.x, w00, acc0[r]);
            acc0[r] = fmaf(hv.y, w10, acc0[r]);
            acc0[r] = fmaf(hv.z, w20, acc0[r]);
            acc0[r] = fmaf(hv.w, w30, acc0[r]);
            acc1[r] = fmaf(hv.x, w01, acc1[r]);
            acc1[r] = fmaf(hv.y, w11, acc1[r]);
            acc1[r] = fmaf(hv.z, w21, acc1[r]);
            acc1[r] = fmaf(hv.w, w31, acc1[r]);
        }
    }

    const float a10 = a[tx], a11 = a[tx + 32];
    const float a20 = a[OUT_FEATS + tx], a21 = a[OUT_FEATS + tx + 32];

    int nrow = n - row0; if (nrow > BM) nrow = BM;
    #pragma unroll
    for (int r = 0; r < 8; r++) {
        const int row = ty + 4 * r;
        float p1 = acc0[r] * a10 + acc1[r] * a11;
        float p2 = acc0[r] * a20 + acc1[r] * a21;
        #pragma unroll
        for (int off = 16; off; off >>= 1) {
            p1 += __shfl_xor_sync(0xffffffffu, p1, off);
            p2 += __shfl_xor_sync(0xffffffffu, p2, off);
        }
        if (row < nrow) {
            float* dst = g_Wh + (size_t)(row0 + row) * OUT_FEATS;
            dst[tx]      = acc0[r];
            dst[tx + 32] = acc1[r];
            if (tx == 0) { g_s1[row0 + row] = p1; g_s2[row0 + row] = p2; }
        }
    }
}

// ---------------------------------------------------------------------------
// K2: in-degree histogram.  4 edges per thread, vectorized dst loads.
// ---------------------------------------------------------------------------
__global__ __launch_bounds__(256) void k_edge(const int* __restrict__ ei,
                                              int ne, int n) {
    const int q  = blockIdx.x * blockDim.x + threadIdx.x;
    const int e0 = q * 4;
    if (e0 >= ne) return;
    const int is64 = g_is64;
    const int cnt  = (ne - e0 < 4) ? (ne - e0) : 4;

    int d[4];
    if (cnt == 4 && !is64 && ((ne & 3) == 0)) {
        int4 v = *(const int4*)&ei[ne + e0];                // dst[e0..e0+3]
        d[0] = v.x; d[1] = v.y; d[2] = v.z; d[3] = v.w;
    } else if (cnt == 4 && is64 && ((ne & 1) == 0)) {
        int4 v0 = *(const int4*)&ei[2 * (ne + e0)];         // {lo,hi,lo,hi}
        int4 v1 = *(const int4*)&ei[2 * (ne + e0) + 4];
        d[0] = v0.x; d[1] = v0.z; d[2] = v1.x; d[3] = v1.z;
    } else {
        for (int i = 0; i < 4; i++)
            d[i] = (i < cnt) ? (is64 ? ei[2 * (ne + e0 + i)] : ei[ne + e0 + i]) : 0;
    }
    #pragma unroll
    for (int i = 0; i < 4; i++) {
        if (i < cnt) {
            int dst = d[i];
            if ((unsigned)dst >= (unsigned)n) dst = 0;
            atomicAdd(g_cnt + dst, 1);
        }
    }
}

// ---------------------------------------------------------------------------
// K3: exclusive scan of g_cnt -> g_off (+ cursors).  1024 threads, shfl scan.
// ---------------------------------------------------------------------------
__global__ __launch_bounds__(1024) void k_scan(int n) {
    const int T  = 1024;
    const int t  = threadIdx.x;
    const int CH = (n + T - 1) / T;
    int beg = t * CH;  if (beg > n) beg = n;
    int end = beg + CH; if (end > n) end = n;

    int sum = 0;
    for (int i = beg; i < end; i++) sum += g_cnt[i];

    const int lane = t & 31, wid = t >> 5;
    int v = sum;
    #pragma unroll
    for (int off = 1; off < 32; off <<= 1) {
        int u = __shfl_up_sync(0xffffffffu, v, off);
        if (lane >= off) v += u;
    }
    __shared__ int wsum[32];
    if (lane == 31) wsum[wid] = v;
    __syncthreads();
    if (wid == 0) {
        int w = wsum[lane];
        #pragma unroll
        for (int off = 1; off < 32; off <<= 1) {
            int u = __shfl_up_sync(0xffffffffu, w, off);
            if (lane >= off) w += u;
        }
        wsum[lane] = w;
    }
    __syncthreads();
    const int incl = v + (wid ? wsum[wid - 1] : 0);   // inclusive prefix
    int run = incl - sum;                             // exclusive

    for (int i = beg; i < end; i++) {
        int c = g_cnt[i];
        g_off[i] = run;
        g_cur[i] = run;
        run += c;
    }
    if (t == T - 1) g_off[n] = incl;
}

// ---------------------------------------------------------------------------
// K4: fill CSR with inline attention numerator (one int2 store per edge):
//     slot = cur[dst]++;  cedge[slot] = {src, bits(exp(lrelu(s1+s2)))}
// ---------------------------------------------------------------------------
__global__ __launch_bounds__(256) void k_fill(const int* __restrict__ ei,
                                              int ne, int n) {
    const int e = blockIdx.x * blockDim.x + threadIdx.x;
    if (e >= ne) return;
    const int is64 = g_is64;
    int src, dst;
    if (is64) { src = ei[2 * e]; dst = ei[2 * (ne + e)]; }
    else      { src = ei[e];     dst = ei[ne + e]; }
    if ((unsigned)src >= (unsigned)n) src = 0;
    if ((unsigned)dst >= (unsigned)n) dst = 0;

    const float s  = g_s1[src] + g_s2[dst];
    const float lr = s > 0.0f ? s : ALPHA * s;
    const int slot = atomicAdd(g_cur + dst, 1);
    g_cedge[slot] = make_int2(src, __float_as_int(expf(lr)));
}

// ---------------------------------------------------------------------------
// K5: gather per dst node (16 threads/node, one float4 slice per lane),
//     4-wide unrolled edge loop for MLP.  out = elu(acc / dsum).
// ---------------------------------------------------------------------------
__global__ __launch_bounds__(256) void k_gather(float* __restrict__ out, int n) {
    const int gt   = blockIdx.x * blockDim.x + threadIdx.x;
    const int node = gt >> 4;
    const int lane = gt & 15;
    if (node >= n) return;

    const int beg = g_off[node];
    const int end = g_off[node + 1];

    const float4* __restrict__ Wh4 = (const float4*)g_Wh;
    const int2*   __restrict__ ced = g_cedge;
    float4 acc = make_float4(0.f, 0.f, 0.f, 0.f);
    float  dsum = 0.0f;

    int j = beg;
    for (; j + 4 <= end; j += 4) {
        const int2 c0 = ced[j],     c1 = ced[j + 1];
        const int2 c2 = ced[j + 2], c3 = ced[j + 3];
        const float4 v0 = Wh4[(size_t)c0.x * (OUT_FEATS / 4) + lane];
        const float4 v1 = Wh4[(size_t)c1.x * (OUT_FEATS / 4) + lane];
        const float4 v2 = Wh4[(size_t)c2.x * (OUT_FEATS / 4) + lane];
        const float4 v3 = Wh4[(size_t)c3.x * (OUT_FEATS / 4) + lane];
        const float w0 = __int_as_float(c0.y), w1 = __int_as_float(c1.y);
        const float w2 = __int_as_float(c2.y), w3 = __int_as_float(c3.y);

        acc.x = fmaf(w0, v0.x, acc.x); acc.y = fmaf(w0, v0.y, acc.y);
        acc.z = fmaf(w0, v0.z, acc.z); acc.w = fmaf(w0, v0.w, acc.w);
        acc.x = fmaf(w1, v1.x, acc.x); acc.y = fmaf(w1, v1.y, acc.y);
        acc.z = fmaf(w1, v1.z, acc.z); acc.w = fmaf(w1, v1.w, acc.w);
        acc.x = fmaf(w2, v2.x, acc.x); acc.y = fmaf(w2, v2.y, acc.y);
        acc.z = fmaf(w2, v2.z, acc.z); acc.w = fmaf(w2, v2.w, acc.w);
        acc.x = fmaf(w3, v3.x, acc.x); acc.y = fmaf(w3, v3.y, acc.y);
        acc.z = fmaf(w3, v3.z, acc.z); acc.w = fmaf(w3, v3.w, acc.w);
        dsum += (w0 + w1) + (w2 + w3);
    }
    for (; j < end; j++) {
        const int2 c = ced[j];
        const float w = __int_as_float(c.y);
        const float4 v = Wh4[(size_t)c.x * (OUT_FEATS / 4) + lane];
        acc.x = fmaf(w, v.x, acc.x);
        acc.y = fmaf(w, v.y, acc.y);
        acc.z = fmaf(w, v.z, acc.z);
        acc.w = fmaf(w, v.w, acc.w);
        dsum += w;
    }

    const float inv = (end > beg) ? (1.0f / dsum) : 0.0f;
    float4 r;
    r.x = acc.x * inv;  r.y = acc.y * inv;
    r.z = acc.z * inv;  r.w = acc.w * inv;
    r.x = r.x > 0.f ? r.x : expm1f(r.x);
    r.y = r.y > 0.f ? r.y : expm1f(r.y);
    r.z = r.z > 0.f ? r.z : expm1f(r.z);
    r.w = r.w > 0.f ? r.w : expm1f(r.w);

    ((float4*)out)[(size_t)node * (OUT_FEATS / 4) + lane] = r;
}

// ---------------------------------------------------------------------------
// Launcher.  Inputs identified by element count (robust to ordering).
// ---------------------------------------------------------------------------
extern "C" void kernel_launch(void* const* d_in, const int* in_sizes, int n_in,
                              void* d_out, int out_size) {
    const float* h  = nullptr;
    const int*   ei = nullptr;
    const float* W  = nullptr;
    const float* a  = nullptr;
    int n = N_NODES, ne = N_EDGES;

    for (int i = 0; i < n_in; i++) {
        const int sz = in_sizes[i];
        if (sz == IN_FEATS * OUT_FEATS)       W  = (const float*)d_in[i];
        else if (sz == 2 * OUT_FEATS)         a  = (const float*)d_in[i];
        else if (sz == 2 * N_EDGES)           { ei = (const int*)d_in[i]; ne = sz / 2; }
        else if (sz == 4 * N_EDGES)           { ei = (const int*)d_in[i]; ne = sz / 4; }
        else                                  { h  = (const float*)d_in[i]; n = sz / IN_FEATS; }
    }
    if (n > N_NODES)  n  = N_NODES;   // protect static scratch
    if (ne > N_EDGES) ne = N_EDGES;

    k_init  <<<(n + 255) / 256, 256>>>(ei, n);
    k_gemm  <<<(n + BM - 1) / BM, 128>>>(h, W, a, n);
    k_edge  <<<(ne / 4 + 255) / 256, 256>>>(ei, ne, n);
    k_scan  <<<1, 1024>>>(n);
    k_fill  <<<(ne + 255) / 256, 256>>>(ei, ne, n);
    k_gather<<<(n * 16 + 255) / 256, 256>>>((float*)d_out, n);
}

// round 12
// speedup vs baseline: 2.0446x; 1.8662x over previous
#include <cuda_runtime.h>
#include <cuda_bf16.h>
#include <math.h>

// Problem constants (GraphAttentionLayer_85572928406097)
#define N_NODES   50000
#define N_EDGES   800000
#define IN_FEATS  128
#define OUT_FEATS 64
#define ALPHA     0.2f

#define SCAN_CHUNK 1024                     // elements per scan block
#define SCAN_NB    ((N_NODES + SCAN_CHUNK - 1) / SCAN_CHUNK)   // 49

// ---------------------------------------------------------------------------
// Scratch (__device__ globals; 16B-aligned)
// ---------------------------------------------------------------------------
__device__ __align__(16) float g_Wh[(size_t)N_NODES * OUT_FEATS];  // 12.8 MB
__device__ __align__(16) float g_s1[N_NODES];
__device__ __align__(16) float g_s2[N_NODES];
__device__ __align__(16) int   g_cnt[N_NODES];                     // in-degree
__device__ __align__(16) int   g_off[N_NODES + 4];                 // CSR offsets
__device__ __align__(16) int   g_cur[N_NODES];                     // cursors
__device__ __align__(16) int2  g_cedge[N_EDGES];                   // {src, exp bits}
__device__ __align__(16) int   g_bsum[256];                        // scan partials
__device__ __align__(16) int   g_boff[256];                        // scan offsets
__device__ int g_is64;                                             // edge dtype

// ---------------------------------------------------------------------------
// K_init: zero histogram + dtype detect (block 0 probes 256 odd words;
// int64 values < 2^31 have all-zero odd words, int32 node ids do not).
// ---------------------------------------------------------------------------
__global__ void k_init(const int* __restrict__ ei, int n) {
    const int i = blockIdx.x * blockDim.x + threadIdx.x;
    if (i < n) g_cnt[i] = 0;
    if (blockIdx.x == 0) {
        __shared__ int any;
        if (threadIdx.x == 0) any = 0;
        __syncthreads();
        if (ei[2 * threadIdx.x + 1] != 0) atomicOr(&any, 1);
        __syncthreads();
        if (threadIdx.x == 0) g_is64 = (any == 0) ? 1 : 0;
    }
}

// ---------------------------------------------------------------------------
// K1: Wh = h @ W  with fused score epilogue (s1 = Wh·a1, s2 = Wh·a2).
//     BM=32 rows x 64 cols, K=128.  128 threads; each owns 8 rows x 2 cols.
// ---------------------------------------------------------------------------
#define BM 32
__global__ __launch_bounds__(128) void k_gemm(const float* __restrict__ h,
                                              const float* __restrict__ W,
                                              const float* __restrict__ a,
                                              int n) {
    __shared__ float hs[BM][IN_FEATS];        // 16 KB
    __shared__ float Ws[IN_FEATS][OUT_FEATS]; // 32 KB

    const int tid  = threadIdx.x;
    const int row0 = blockIdx.x * BM;

    {
        const float4* W4  = (const float4*)W;
        float4*       Ws4 = (float4*)&Ws[0][0];
        #pragma unroll
        for (int i = 0; i < 16; i++) Ws4[tid + i * 128] = W4[tid + i * 128];
    }
    {
        const float4* h4  = (const float4*)(h + (size_t)row0 * IN_FEATS);
        float4*       hs4 = (float4*)&hs[0][0];
        int nrow = n - row0; if (nrow > BM) nrow = BM;
        int nvec = nrow * (IN_FEATS / 4);
        #pragma unroll
        for (int i = 0; i < 8; i++) {
            int idx = tid + i * 128;
            float4 v = make_float4(0.f, 0.f, 0.f, 0.f);
            if (idx < nvec) v = h4[idx];
            hs4[idx] = v;
        }
    }
    __syncthreads();

    const int tx = tid & 31;   // lane: cols {tx, tx+32}
    const int ty = tid >> 5;   // warp: rows ty + 4*r

    float acc0[8], acc1[8];
    #pragma unroll
    for (int r = 0; r < 8; r++) { acc0[r] = 0.f; acc1[r] = 0.f; }

    #pragma unroll
    for (int k = 0; k < IN_FEATS; k += 4) {
        const float w00 = Ws[k + 0][tx], w01 = Ws[k + 0][tx + 32];
        const float w10 = Ws[k + 1][tx], w11 = Ws[k + 1][tx + 32];
        const float w20 = Ws[k + 2][tx], w21 = Ws[k + 2][tx + 32];
        const float w30 = Ws[k + 3][tx], w31 = Ws[k + 3][tx + 32];
        #pragma unroll
        for (int r = 0; r < 8; r++) {
            const float4 hv = *(const float4*)&hs[ty + 4 * r][k];
            acc0[r] = fmaf(hv.x, w00, acc0[r]);
            acc0[r] = fmaf(hv.y, w10, acc0[r]);
            acc0[r] = fmaf(hv.z, w20, acc0[r]);
            acc0[r] = fmaf(hv.w, w30, acc0[r]);
            acc1[r] = fmaf(hv.x, w01, acc1[r]);
            acc1[r] = fmaf(hv.y, w11, acc1[r]);
            acc1[r] = fmaf(hv.z, w21, acc1[r]);
            acc1[r] = fmaf(hv.w, w31, acc1[r]);
        }
    }

    const float a10 = a[tx], a11 = a[tx + 32];
    const float a20 = a[OUT_FEATS + tx], a21 = a[OUT_FEATS + tx + 32];

    int nrow = n - row0; if (nrow > BM) nrow = BM;
    #pragma unroll
    for (int r = 0; r < 8; r++) {
        const int row = ty + 4 * r;
        float p1 = acc0[r] * a10 + acc1[r] * a11;
        float p2 = acc0[r] * a20 + acc1[r] * a21;
        #pragma unroll
        for (int off = 16; off; off >>= 1) {
            p1 += __shfl_xor_sync(0xffffffffu, p1, off);
            p2 += __shfl_xor_sync(0xffffffffu, p2, off);
        }
        if (row < nrow) {
            float* dst = g_Wh + (size_t)(row0 + row) * OUT_FEATS;
            dst[tx]      = acc0[r];
            dst[tx + 32] = acc1[r];
            if (tx == 0) { g_s1[row0 + row] = p1; g_s2[row0 + row] = p2; }
        }
    }
}

// ---------------------------------------------------------------------------
// K2: in-degree histogram.  4 edges per thread, vectorized dst loads.
// ---------------------------------------------------------------------------
__global__ __launch_bounds__(256) void k_edge(const int* __restrict__ ei,
                                              int ne, int n) {
    const int q  = blockIdx.x * blockDim.x + threadIdx.x;
    const int e0 = q * 4;
    if (e0 >= ne) return;
    const int is64 = g_is64;
    const int cnt  = (ne - e0 < 4) ? (ne - e0) : 4;

    int d[4];
    if (cnt == 4 && !is64 && ((ne & 3) == 0)) {
        int4 v = *(const int4*)&ei[ne + e0];                // dst[e0..e0+3]
        d[0] = v.x; d[1] = v.y; d[2] = v.z; d[3] = v.w;
    } else if (cnt == 4 && is64 && ((ne & 1) == 0)) {
        int4 v0 = *(const int4*)&ei[2 * (ne + e0)];         // {lo,hi,lo,hi}
        int4 v1 = *(const int4*)&ei[2 * (ne + e0) + 4];
        d[0] = v0.x; d[1] = v0.z; d[2] = v1.x; d[3] = v1.z;
    } else {
        for (int i = 0; i < 4; i++)
            d[i] = (i < cnt) ? (is64 ? ei[2 * (ne + e0 + i)] : ei[ne + e0 + i]) : 0;
    }
    #pragma unroll
    for (int i = 0; i < 4; i++) {
        if (i < cnt) {
            int dst = d[i];
            if ((unsigned)dst >= (unsigned)n) dst = 0;
            atomicAdd(g_cnt + dst, 1);
        }
    }
}

// ---------------------------------------------------------------------------
// Scan, pass A: per-block local exclusive scan of a 1024-count chunk.
// 256 threads x 4 counts each.  Writes local prefixes to g_off, block total
// to g_bsum[blockIdx].
// ---------------------------------------------------------------------------
__global__ __launch_bounds__(256) void k_scanA(int n) {
    const int b  = blockIdx.x;
    const int t  = threadIdx.x;
    const int i0 = b * SCAN_CHUNK + t * 4;

    int4 c = make_int4(0, 0, 0, 0);
    if (i0 + 3 < n) {
        c = *(const int4*)&g_cnt[i0];
    } else {
        if (i0 + 0 < n) c.x = g_cnt[i0 + 0];
        if (i0 + 1 < n) c.y = g_cnt[i0 + 1];
        if (i0 + 2 < n) c.z = g_cnt[i0 + 2];
        if (i0 + 3 < n) c.w = g_cnt[i0 + 3];
    }
    const int s = c.x + c.y + c.z + c.w;

    // block-wide inclusive scan of s (shfl within warp, smem across warps)
    const int lane = t & 31, wid = t >> 5;
    int v = s;
    #pragma unroll
    for (int off = 1; off < 32; off <<= 1) {
        int u = __shfl_up_sync(0xffffffffu, v, off);
        if (lane >= off) v += u;
    }
    __shared__ int wsum[8];
    if (lane == 31) wsum[wid] = v;
    __syncthreads();
    if (wid == 0 && lane < 8) {
        int w = wsum[lane];
        #pragma unroll
        for (int off = 1; off < 8; off <<= 1) {
            int u = __shfl_up_sync(0xffu, w, off);
            if (lane >= off) w += u;
        }
        wsum[lane] = w;
    }
    __syncthreads();
    const int incl = v + (wid ? wsum[wid - 1] : 0);
    const int excl = incl - s;

    int4 p;
    p.x = excl;
    p.y = excl + c.x;
    p.z = p.y + c.y;
    p.w = p.z + c.z;
    if (i0 + 3 < n) {
        *(int4*)&g_off[i0] = p;
    } else {
        if (i0 + 0 < n) g_off[i0 + 0] = p.x;
        if (i0 + 1 < n) g_off[i0 + 1] = p.y;
        if (i0 + 2 < n) g_off[i0 + 2] = p.z;
        if (i0 + 3 < n) g_off[i0 + 3] = p.w;
    }
    if (t == 255) g_bsum[b] = incl;   // block total
}

// ---------------------------------------------------------------------------
// Scan, pass B: single block scans the <=256 block totals -> g_boff
// (exclusive).  Writes grand total to g_off[n].
// ---------------------------------------------------------------------------
__global__ __launch_bounds__(256) void k_scanB(int nb, int n) {
    const int t = threadIdx.x;
    const int s = (t < nb) ? g_bsum[t] : 0;

    const int lane = t & 31, wid = t >> 5;
    int v = s;
    #pragma unroll
    for (int off = 1; off < 32; off <<= 1) {
        int u = __shfl_up_sync(0xffffffffu, v, off);
        if (lane >= off) v += u;
    }
    __shared__ int wsum[8];
    if (lane == 31) wsum[wid] = v;
    __syncthreads();
    if (wid == 0 && lane < 8) {
        int w = wsum[lane];
        #pragma unroll
        for (int off = 1; off < 8; off <<= 1) {
            int u = __shfl_up_sync(0xffu, w, off);
            if (lane >= off) w += u;
        }
        wsum[lane] = w;
    }
    __syncthreads();
    const int incl = v + (wid ? wsum[wid - 1] : 0);
    if (t < nb) g_boff[t] = incl - s;
    if (t == nb - 1) g_off[n] = incl;
}

// ---------------------------------------------------------------------------
// Scan, pass C: add block offset; materialize final g_off and g_cur.
// ---------------------------------------------------------------------------
__global__ __launch_bounds__(256) void k_scanC(int n) {
    const int b   = blockIdx.x;
    const int t   = threadIdx.x;
    const int add = g_boff[b];
    const int i0  = b * SCAN_CHUNK + t * 4;

    if (i0 + 3 < n) {
        int4 p = *(const int4*)&g_off[i0];
        p.x += add; p.y += add; p.z += add; p.w += add;
        *(int4*)&g_off[i0] = p;
        *(int4*)&g_cur[i0] = p;
    } else {
        #pragma unroll
        for (int k = 0; k < 4; k++) {
            if (i0 + k < n) {
                int v = g_off[i0 + k] + add;
                g_off[i0 + k] = v;
                g_cur[i0 + k] = v;
            }
        }
    }
}

// ---------------------------------------------------------------------------
// K4: fill CSR with inline attention numerator (one int2 store per edge):
//     slot = cur[dst]++;  cedge[slot] = {src, bits(exp(lrelu(s1+s2)))}
// ---------------------------------------------------------------------------
__global__ __launch_bounds__(256) void k_fill(const int* __restrict__ ei,
                                              int ne, int n) {
    const int e = blockIdx.x * blockDim.x + threadIdx.x;
    if (e >= ne) return;
    const int is64 = g_is64;
    int src, dst;
    if (is64) { src = ei[2 * e]; dst = ei[2 * (ne + e)]; }
    else      { src = ei[e];     dst = ei[ne + e]; }
    if ((unsigned)src >= (unsigned)n) src = 0;
    if ((unsigned)dst >= (unsigned)n) dst = 0;

    const float s  = g_s1[src] + g_s2[dst];
    const float lr = s > 0.0f ? s : ALPHA * s;
    const int slot = atomicAdd(g_cur + dst, 1);
    g_cedge[slot] = make_int2(src, __float_as_int(expf(lr)));
}

// ---------------------------------------------------------------------------
// K5: gather per dst node (16 threads/node, one float4 slice per lane),
//     4-wide unrolled edge loop for MLP.  out = elu(acc / dsum).
// ---------------------------------------------------------------------------
__global__ __launch_bounds__(256) void k_gather(float* __restrict__ out, int n) {
    const int gt   = blockIdx.x * blockDim.x + threadIdx.x;
    const int node = gt >> 4;
    const int lane = gt & 15;
    if (node >= n) return;

    const int beg = g_off[node];
    const int end = g_off[node + 1];

    const float4* __restrict__ Wh4 = (const float4*)g_Wh;
    const int2*   __restrict__ ced = g_cedge;
    float4 acc = make_float4(0.f, 0.f, 0.f, 0.f);
    float  dsum = 0.0f;

    int j = beg;
    for (; j + 4 <= end; j += 4) {
        const int2 c0 = ced[j],     c1 = ced[j + 1];
        const int2 c2 = ced[j + 2], c3 = ced[j + 3];
        const float4 v0 = Wh4[(size_t)c0.x * (OUT_FEATS / 4) + lane];
        const float4 v1 = Wh4[(size_t)c1.x * (OUT_FEATS / 4) + lane];
        const float4 v2 = Wh4[(size_t)c2.x * (OUT_FEATS / 4) + lane];
        const float4 v3 = Wh4[(size_t)c3.x * (OUT_FEATS / 4) + lane];
        const float w0 = __int_as_float(c0.y), w1 = __int_as_float(c1.y);
        const float w2 = __int_as_float(c2.y), w3 = __int_as_float(c3.y);

        acc.x = fmaf(w0, v0.x, acc.x); acc.y = fmaf(w0, v0.y, acc.y);
        acc.z = fmaf(w0, v0.z, acc.z); acc.w = fmaf(w0, v0.w, acc.w);
        acc.x = fmaf(w1, v1.x, acc.x); acc.y = fmaf(w1, v1.y, acc.y);
        acc.z = fmaf(w1, v1.z, acc.z); acc.w = fmaf(w1, v1.w, acc.w);
        acc.x = fmaf(w2, v2.x, acc.x); acc.y = fmaf(w2, v2.y, acc.y);
        acc.z = fmaf(w2, v2.z, acc.z); acc.w = fmaf(w2, v2.w, acc.w);
        acc.x = fmaf(w3, v3.x, acc.x); acc.y = fmaf(w3, v3.y, acc.y);
        acc.z = fmaf(w3, v3.z, acc.z); acc.w = fmaf(w3, v3.w, acc.w);
        dsum += (w0 + w1) + (w2 + w3);
    }
    for (; j < end; j++) {
        const int2 c = ced[j];
        const float w = __int_as_float(c.y);
        const float4 v = Wh4[(size_t)c.x * (OUT_FEATS / 4) + lane];
        acc.x = fmaf(w, v.x, acc.x);
        acc.y = fmaf(w, v.y, acc.y);
        acc.z = fmaf(w, v.z, acc.z);
        acc.w = fmaf(w, v.w, acc.w);
        dsum += w;
    }

    const float inv = (end > beg) ? (1.0f / dsum) : 0.0f;
    float4 r;
    r.x = acc.x * inv;  r.y = acc.y * inv;
    r.z = acc.z * inv;  r.w = acc.w * inv;
    r.x = r.x > 0.f ? r.x : expm1f(r.x);
    r.y = r.y > 0.f ? r.y : expm1f(r.y);
    r.z = r.z > 0.f ? r.z : expm1f(r.z);
    r.w = r.w > 0.f ? r.w : expm1f(r.w);

    ((float4*)out)[(size_t)node * (OUT_FEATS / 4) + lane] = r;
}

// ---------------------------------------------------------------------------
// Launcher.  Inputs identified by element count (robust to ordering).
// ---------------------------------------------------------------------------
extern "C" void kernel_launch(void* const* d_in, const int* in_sizes, int n_in,
                              void* d_out, int out_size) {
    const float* h  = nullptr;
    const int*   ei = nullptr;
    const float* W  = nullptr;
    const float* a  = nullptr;
    int n = N_NODES, ne = N_EDGES;

    for (int i = 0; i < n_in; i++) {
        const int sz = in_sizes[i];
        if (sz == IN_FEATS * OUT_FEATS)       W  = (const float*)d_in[i];
        else if (sz == 2 * OUT_FEATS)         a  = (const float*)d_in[i];
        else if (sz == 2 * N_EDGES)           { ei = (const int*)d_in[i]; ne = sz / 2; }
        else if (sz == 4 * N_EDGES)           { ei = (const int*)d_in[i]; ne = sz / 4; }
        else                                  { h  = (const float*)d_in[i]; n = sz / IN_FEATS; }
    }
    if (n > N_NODES)  n  = N_NODES;   // protect static scratch
    if (ne > N_EDGES) ne = N_EDGES;

    const int nb = (n + SCAN_CHUNK - 1) / SCAN_CHUNK;

    k_init  <<<(n + 255) / 256, 256>>>(ei, n);
    k_gemm  <<<(n + BM - 1) / BM, 128>>>(h, W, a, n);
    k_edge  <<<(ne / 4 + 255) / 256, 256>>>(ei, ne, n);
    k_scanA <<<nb, 256>>>(n);
    k_scanB <<<1, 256>>>(nb, n);
    k_scanC <<<nb, 256>>>(n);
    k_fill  <<<(ne + 255) / 256, 256>>>(ei, ne, n);
    k_gather<<<(n * 16 + 255) / 256, 256>>>((float*)d_out, n);
}

// round 13
// speedup vs baseline: 2.0560x; 1.0056x over previous
#include <cuda_runtime.h>
#include <cuda_bf16.h>
#include <math.h>

// Problem constants (GraphAttentionLayer_85572928406097)
#define N_NODES   50000
#define N_EDGES   800000
#define IN_FEATS  128
#define OUT_FEATS 64
#define ALPHA     0.2f

#define SCAN_CHUNK 1024                     // elements per scan block

// ---------------------------------------------------------------------------
// Scratch (__device__ globals; zero-initialized at load; 16B-aligned)
// ---------------------------------------------------------------------------
__device__ __align__(16) float g_Wh[(size_t)N_NODES * OUT_FEATS];  // 12.8 MB
__device__ __align__(16) float g_s1[N_NODES];
__device__ __align__(16) float g_s2[N_NODES];
__device__ __align__(16) int   g_cnt[N_NODES];     // in-degree; ZERO at entry
                                                   // (zero-init first run, re-zeroed by k_scan)
__device__ __align__(16) int   g_off[N_NODES + 4]; // CSR offsets
__device__ __align__(16) int   g_cur[N_NODES];     // cursors
__device__ __align__(16) int2  g_cedge[N_EDGES];   // {src, exp bits}
__device__ __align__(16) int   g_bsum[256];        // scan publish: total+1 (0 = not ready)
__device__ int g_is64;                             // edge dtype

// ---------------------------------------------------------------------------
// K_init (1 block): zero scan-publish slots + edge dtype detect.
// int64 values < 2^31 have all-zero odd 32-bit words; int32 ids do not.
// ---------------------------------------------------------------------------
__global__ void k_init(const int* __restrict__ ei) {
    g_bsum[threadIdx.x] = 0;
    __shared__ int any;
    if (threadIdx.x == 0) any = 0;
    __syncthreads();
    if (ei[2 * threadIdx.x + 1] != 0) atomicOr(&any, 1);
    __syncthreads();
    if (threadIdx.x == 0) g_is64 = (any == 0) ? 1 : 0;
}

// ---------------------------------------------------------------------------
// K1: Wh = h @ W  with fused score epilogue (s1 = Wh·a1, s2 = Wh·a2).
//     BM=32 rows x 64 cols, K=128.  128 threads; each owns 8 rows x 2 cols.
// ---------------------------------------------------------------------------
#define BM 32
__global__ __launch_bounds__(128) void k_gemm(const float* __restrict__ h,
                                              const float* __restrict__ W,
                                              const float* __restrict__ a,
                                              int n) {
    __shared__ float hs[BM][IN_FEATS];        // 16 KB
    __shared__ float Ws[IN_FEATS][OUT_FEATS]; // 32 KB

    const int tid  = threadIdx.x;
    const int row0 = blockIdx.x * BM;

    {
        const float4* W4  = (const float4*)W;
        float4*       Ws4 = (float4*)&Ws[0][0];
        #pragma unroll
        for (int i = 0; i < 16; i++) Ws4[tid + i * 128] = W4[tid + i * 128];
    }
    {
        const float4* h4  = (const float4*)(h + (size_t)row0 * IN_FEATS);
        float4*       hs4 = (float4*)&hs[0][0];
        int nrow = n - row0; if (nrow > BM) nrow = BM;
        int nvec = nrow * (IN_FEATS / 4);
        #pragma unroll
        for (int i = 0; i < 8; i++) {
            int idx = tid + i * 128;
            float4 v = make_float4(0.f, 0.f, 0.f, 0.f);
            if (idx < nvec) v = h4[idx];
            hs4[idx] = v;
        }
    }
    __syncthreads();

    const int tx = tid & 31;   // lane: cols {tx, tx+32}
    const int ty = tid >> 5;   // warp: rows ty + 4*r

    float acc0[8], acc1[8];
    #pragma unroll
    for (int r = 0; r < 8; r++) { acc0[r] = 0.f; acc1[r] = 0.f; }

    #pragma unroll
    for (int k = 0; k < IN_FEATS; k += 4) {
        const float w00 = Ws[k + 0][tx], w01 = Ws[k + 0][tx + 32];
        const float w10 = Ws[k + 1][tx], w11 = Ws[k + 1][tx + 32];
        const float w20 = Ws[k + 2][tx], w21 = Ws[k + 2][tx + 32];
        const float w30 = Ws[k + 3][tx], w31 = Ws[k + 3][tx + 32];
        #pragma unroll
        for (int r = 0; r < 8; r++) {
            const float4 hv = *(const float4*)&hs[ty + 4 * r][k];
            acc0[r] = fmaf(hv.x, w00, acc0[r]);
            acc0[r] = fmaf(hv.y, w10, acc0[r]);
            acc0[r] = fmaf(hv.z, w20, acc0[r]);
            acc0[r] = fmaf(hv.w, w30, acc0[r]);
            acc1[r] = fmaf(hv.x, w01, acc1[r]);
            acc1[r] = fmaf(hv.y, w11, acc1[r]);
            acc1[r] = fmaf(hv.z, w21, acc1[r]);
            acc1[r] = fmaf(hv.w, w31, acc1[r]);
        }
    }

    const float a10 = a[tx], a11 = a[tx + 32];
    const float a20 = a[OUT_FEATS + tx], a21 = a[OUT_FEATS + tx + 32];

    int nrow = n - row0; if (nrow > BM) nrow = BM;
    #pragma unroll
    for (int r = 0; r < 8; r++) {
        const int row = ty + 4 * r;
        float p1 = acc0[r] * a10 + acc1[r] * a11;
        float p2 = acc0[r] * a20 + acc1[r] * a21;
        #pragma unroll
        for (int off = 16; off; off >>= 1) {
            p1 += __shfl_xor_sync(0xffffffffu, p1, off);
            p2 += __shfl_xor_sync(0xffffffffu, p2, off);
        }
        if (row < nrow) {
            float* dst = g_Wh + (size_t)(row0 + row) * OUT_FEATS;
            dst[tx]      = acc0[r];
            dst[tx + 32] = acc1[r];
            if (tx == 0) { g_s1[row0 + row] = p1; g_s2[row0 + row] = p2; }
        }
    }
}

// ---------------------------------------------------------------------------
// K2: in-degree histogram.  4 edges per thread, vectorized dst loads.
//     Requires g_cnt == 0 at entry (zero-init / re-zeroed by k_scan).
// ---------------------------------------------------------------------------
__global__ __launch_bounds__(256) void k_edge(const int* __restrict__ ei,
                                              int ne, int n) {
    const int q  = blockIdx.x * blockDim.x + threadIdx.x;
    const int e0 = q * 4;
    if (e0 >= ne) return;
    const int is64 = g_is64;
    const int cnt  = (ne - e0 < 4) ? (ne - e0) : 4;

    int d[4];
    if (cnt == 4 && !is64 && ((ne & 3) == 0)) {
        int4 v = *(const int4*)&ei[ne + e0];
        d[0] = v.x; d[1] = v.y; d[2] = v.z; d[3] = v.w;
    } else if (cnt == 4 && is64 && ((ne & 1) == 0)) {
        int4 v0 = *(const int4*)&ei[2 * (ne + e0)];
        int4 v1 = *(const int4*)&ei[2 * (ne + e0) + 4];
        d[0] = v0.x; d[1] = v0.z; d[2] = v1.x; d[3] = v1.z;
    } else {
        for (int i = 0; i < 4; i++)
            d[i] = (i < cnt) ? (is64 ? ei[2 * (ne + e0 + i)] : ei[ne + e0 + i]) : 0;
    }
    #pragma unroll
    for (int i = 0; i < 4; i++) {
        if (i < cnt) {
            int dst = d[i];
            if ((unsigned)dst >= (unsigned)n) dst = 0;
            atomicAdd(g_cnt + dst, 1);
        }
    }
}

// ---------------------------------------------------------------------------
// K3: fused exclusive scan (single kernel, decoupled publish).
//     Each of nb (<=49) blocks:
//       1. local exclusive scan of its 1024-count chunk
//       2. publish block total+1 to g_bsum[b]  (0 = not ready)
//       3. poll predecessors, reduce their totals -> add
//       4. write g_off/g_cur = local + add; zero g_cnt for next replay
//     All nb blocks are co-resident (nb << 148) so polling cannot deadlock.
// ---------------------------------------------------------------------------
__global__ __launch_bounds__(256) void k_scan(int nb, int n) {
    const int b  = blockIdx.x;
    const int t  = threadIdx.x;
    const int i0 = b * SCAN_CHUNK + t * 4;

    int4 c = make_int4(0, 0, 0, 0);
    if (i0 + 3 < n) {
        c = *(const int4*)&g_cnt[i0];
    } else {
        if (i0 + 0 < n) c.x = g_cnt[i0 + 0];
        if (i0 + 1 < n) c.y = g_cnt[i0 + 1];
        if (i0 + 2 < n) c.z = g_cnt[i0 + 2];
        if (i0 + 3 < n) c.w = g_cnt[i0 + 3];
    }
    const int s = c.x + c.y + c.z + c.w;

    // block-wide inclusive scan of s
    const int lane = t & 31, wid = t >> 5;
    int v = s;
    #pragma unroll
    for (int off = 1; off < 32; off <<= 1) {
        int u = __shfl_up_sync(0xffffffffu, v, off);
        if (lane >= off) v += u;
    }
    __shared__ int wsum[8];
    if (lane == 31) wsum[wid] = v;
    __syncthreads();
    if (wid == 0 && lane < 8) {
        int w = wsum[lane];
        #pragma unroll
        for (int off = 1; off < 8; off <<= 1) {
            int u = __shfl_up_sync(0xffu, w, off);
            if (lane >= off) w += u;
        }
        wsum[lane] = w;
    }
    __syncthreads();
    const int incl = v + (wid ? wsum[wid - 1] : 0);
    const int excl = incl - s;

    // publish this block's total (+1 so 0 means "not ready")
    __shared__ int blk_total;
    if (t == 255) { blk_total = incl; atomicExch(&g_bsum[b], incl + 1); }

    // predecessor reduction (threads t < b poll & fetch)
    int pv = 0;
    if (t < b) {
        int x;
        do { x = atomicAdd(&g_bsum[t], 0); } while (x == 0);
        pv = x - 1;
    }
    #pragma unroll
    for (int off = 16; off; off >>= 1)
        pv += __shfl_xor_sync(0xffffffffu, pv, off);
    __shared__ int wred[8];
    if (lane == 0) wred[wid] = pv;
    __syncthreads();
    __shared__ int s_add;
    if (t == 0) {
        int a = 0;
        #pragma unroll
        for (int i = 0; i < 8; i++) a += wred[i];
        s_add = a;
    }
    __syncthreads();
    const int add = s_add;

    int4 p;
    p.x = excl + add;
    p.y = p.x + c.x;
    p.z = p.y + c.y;
    p.w = p.z + c.z;
    const int4 z = make_int4(0, 0, 0, 0);
    if (i0 + 3 < n) {
        *(int4*)&g_off[i0] = p;
        *(int4*)&g_cur[i0] = p;
        *(int4*)&g_cnt[i0] = z;          // reset for next replay
    } else {
        const int pv4[4] = {p.x, p.y, p.z, p.w};
        #pragma unroll
        for (int k = 0; k < 4; k++) {
            if (i0 + k < n) {
                g_off[i0 + k] = pv4[k];
                g_cur[i0 + k] = pv4[k];
                g_cnt[i0 + k] = 0;
            }
        }
    }
    if (b == nb - 1 && t == 255) g_off[n] = blk_total + add;
}

// ---------------------------------------------------------------------------
// K4: fill CSR, 4 edges per thread.  All scattered s1/s2 loads issued before
//     the atomic+store chain to maximize MLP.
//     slot = cur[dst]++;  cedge[slot] = {src, bits(exp(lrelu(s1+s2)))}
// ---------------------------------------------------------------------------
__global__ __launch_bounds__(256) void k_fill(const int* __restrict__ ei,
                                              int ne, int n) {
    const int q  = blockIdx.x * blockDim.x + threadIdx.x;
    const int e0 = q * 4;
    if (e0 >= ne) return;
    const int is64 = g_is64;
    const int cnt  = (ne - e0 < 4) ? (ne - e0) : 4;

    int sr[4], ds[4];
    if (cnt == 4 && !is64 && ((ne & 3) == 0)) {
        int4 a = *(const int4*)&ei[e0];        // src
        int4 b = *(const int4*)&ei[ne + e0];   // dst
        sr[0] = a.x; sr[1] = a.y; sr[2] = a.z; sr[3] = a.w;
        ds[0] = b.x; ds[1] = b.y; ds[2] = b.z; ds[3] = b.w;
    } else if (cnt == 4 && is64 && ((ne & 1) == 0)) {
        int4 a0 = *(const int4*)&ei[2 * e0];
        int4 a1 = *(const int4*)&ei[2 * e0 + 4];
        int4 b0 = *(const int4*)&ei[2 * (ne + e0)];
        int4 b1 = *(const int4*)&ei[2 * (ne + e0) + 4];
        sr[0] = a0.x; sr[1] = a0.z; sr[2] = a1.x; sr[3] = a1.z;
        ds[0] = b0.x; ds[1] = b0.z; ds[2] = b1.x; ds[3] = b1.z;
    } else {
        for (int i = 0; i < 4; i++) {
            sr[i] = (i < cnt) ? (is64 ? ei[2 * (e0 + i)]      : ei[e0 + i])      : 0;
            ds[i] = (i < cnt) ? (is64 ? ei[2 * (ne + e0 + i)] : ei[ne + e0 + i]) : 0;
        }
    }
    #pragma unroll
    for (int i = 0; i < 4; i++) {
        if ((unsigned)sr[i] >= (unsigned)n) sr[i] = 0;
        if ((unsigned)ds[i] >= (unsigned)n) ds[i] = 0;
    }

    // batch the scattered score loads (8 independent L2 accesses in flight)
    float sv[4], dv[4];
    #pragma unroll
    for (int i = 0; i < 4; i++) {
        sv[i] = g_s1[sr[i]];
        dv[i] = g_s2[ds[i]];
    }
    #pragma unroll
    for (int i = 0; i < 4; i++) {
        if (i < cnt) {
            const float su = sv[i] + dv[i];
            const float lr = su > 0.0f ? su : ALPHA * su;
            const int slot = atomicAdd(g_cur + ds[i], 1);
            g_cedge[slot] = make_int2(sr[i], __float_as_int(__expf(lr)));
        }
    }
}

// ---------------------------------------------------------------------------
// K5: gather per dst node (16 threads/node, one float4 slice per lane),
//     4-wide unrolled edge loop for MLP.  out = elu(acc / dsum).
// ---------------------------------------------------------------------------
__global__ __launch_bounds__(256) void k_gather(float* __restrict__ out, int n) {
    const int gt   = blockIdx.x * blockDim.x + threadIdx.x;
    const int node = gt >> 4;
    const int lane = gt & 15;
    if (node >= n) return;

    const int beg = g_off[node];
    const int end = g_off[node + 1];

    const float4* __restrict__ Wh4 = (const float4*)g_Wh;
    const int2*   __restrict__ ced = g_cedge;
    float4 acc = make_float4(0.f, 0.f, 0.f, 0.f);
    float  dsum = 0.0f;

    int j = beg;
    for (; j + 4 <= end; j += 4) {
        const int2 c0 = ced[j],     c1 = ced[j + 1];
        const int2 c2 = ced[j + 2], c3 = ced[j + 3];
        const float4 v0 = Wh4[(size_t)c0.x * (OUT_FEATS / 4) + lane];
        const float4 v1 = Wh4[(size_t)c1.x * (OUT_FEATS / 4) + lane];
        const float4 v2 = Wh4[(size_t)c2.x * (OUT_FEATS / 4) + lane];
        const float4 v3 = Wh4[(size_t)c3.x * (OUT_FEATS / 4) + lane];
        const float w0 = __int_as_float(c0.y), w1 = __int_as_float(c1.y);
        const float w2 = __int_as_float(c2.y), w3 = __int_as_float(c3.y);

        acc.x = fmaf(w0, v0.x, acc.x); acc.y = fmaf(w0, v0.y, acc.y);
        acc.z = fmaf(w0, v0.z, acc.z); acc.w = fmaf(w0, v0.w, acc.w);
        acc.x = fmaf(w1, v1.x, acc.x); acc.y = fmaf(w1, v1.y, acc.y);
        acc.z = fmaf(w1, v1.z, acc.z); acc.w = fmaf(w1, v1.w, acc.w);
        acc.x = fmaf(w2, v2.x, acc.x); acc.y = fmaf(w2, v2.y, acc.y);
        acc.z = fmaf(w2, v2.z, acc.z); acc.w = fmaf(w2, v2.w, acc.w);
        acc.x = fmaf(w3, v3.x, acc.x); acc.y = fmaf(w3, v3.y, acc.y);
        acc.z = fmaf(w3, v3.z, acc.z); acc.w = fmaf(w3, v3.w, acc.w);
        dsum += (w0 + w1) + (w2 + w3);
    }
    for (; j < end; j++) {
        const int2 c = ced[j];
        const float w = __int_as_float(c.y);
        const float4 v = Wh4[(size_t)c.x * (OUT_FEATS / 4) + lane];
        acc.x = fmaf(w, v.x, acc.x);
        acc.y = fmaf(w, v.y, acc.y);
        acc.z = fmaf(w, v.z, acc.z);
        acc.w = fmaf(w, v.w, acc.w);
        dsum += w;
    }

    const float inv = (end > beg) ? (1.0f / dsum) : 0.0f;
    float4 r;
    r.x = acc.x * inv;  r.y = acc.y * inv;
    r.z = acc.z * inv;  r.w = acc.w * inv;
    r.x = r.x > 0.f ? r.x : expm1f(r.x);
    r.y = r.y > 0.f ? r.y : expm1f(r.y);
    r.z = r.z > 0.f ? r.z : expm1f(r.z);
    r.w = r.w > 0.f ? r.w : expm1f(r.w);

    ((float4*)out)[(size_t)node * (OUT_FEATS / 4) + lane] = r;
}

// ---------------------------------------------------------------------------
// Launcher.  Inputs identified by element count (robust to ordering).
// ---------------------------------------------------------------------------
extern "C" void kernel_launch(void* const* d_in, const int* in_sizes, int n_in,
                              void* d_out, int out_size) {
    const float* h  = nullptr;
    const int*   ei = nullptr;
    const float* W  = nullptr;
    const float* a  = nullptr;
    int n = N_NODES, ne = N_EDGES;

    for (int i = 0; i < n_in; i++) {
        const int sz = in_sizes[i];
        if (sz == IN_FEATS * OUT_FEATS)       W  = (const float*)d_in[i];
        else if (sz == 2 * OUT_FEATS)         a  = (const float*)d_in[i];
        else if (sz == 2 * N_EDGES)           { ei = (const int*)d_in[i]; ne = sz / 2; }
        else if (sz == 4 * N_EDGES)           { ei = (const int*)d_in[i]; ne = sz / 4; }
        else                                  { h  = (const float*)d_in[i]; n = sz / IN_FEATS; }
    }
    if (n > N_NODES)  n  = N_NODES;   // protect static scratch
    if (ne > N_EDGES) ne = N_EDGES;

    const int nb = (n + SCAN_CHUNK - 1) / SCAN_CHUNK;   // 49 (<=256)

    k_init  <<<1, 256>>>(ei);
    k_gemm  <<<(n + BM - 1) / BM, 128>>>(h, W, a, n);
    k_edge  <<<(ne / 4 + 255) / 256, 256>>>(ei, ne, n);
    k_scan  <<<nb, 256>>>(nb, n);
    k_fill  <<<(ne / 4 + 255) / 256, 256>>>(ei, ne, n);
    k_gather<<<(n * 16 + 255) / 256, 256>>>((float*)d_out, n);
}

// round 17
// speedup vs baseline: 2.2776x; 1.1078x over previous
#include <cuda_runtime.h>
#include <cuda_bf16.h>
#include <math.h>

// Problem constants (GraphAttentionLayer_85572928406097)
#define N_NODES   50000
#define N_EDGES   800000
#define IN_FEATS  128
#define OUT_FEATS 64
#define ALPHA     0.2f

#define SCAN_CHUNK 1024                     // elements per scan block

// ---------------------------------------------------------------------------
// Scratch (__device__ globals; zero-initialized at load; 16B-aligned)
// ---------------------------------------------------------------------------
__device__ __align__(16) float g_Wh[(size_t)N_NODES * OUT_FEATS];  // 12.8 MB
__device__ __align__(16) float g_s1[N_NODES];
__device__ __align__(16) float g_s2[N_NODES];
__device__ __align__(16) int   g_cnt[N_NODES];     // in-degree; ZERO at entry
                                                   // (zero-init 1st run, re-zeroed by k_scan)
__device__ __align__(16) int   g_off[N_NODES + 4]; // CSR offsets
__device__ __align__(16) int   g_cur[N_NODES];     // cursors
__device__ __align__(16) int2  g_cedge[N_EDGES];   // {src, exp bits}
__device__ __align__(16) int   g_bsum[256];        // scan publish: total+1 (0 = not ready)
                                                   // (zero-init 1st run, re-zeroed by k_scan)

// ---------------------------------------------------------------------------
// K1: FUSED  gemm-blocks + edge-histogram-blocks in one launch.
//     blocks [0, ngemm)          : Wh = h@W with fused s1/s2 epilogue
//     blocks [ngemm, ngemm+nedge): in-degree histogram (indep. of gemm)
//     The two block types stress disjoint pipes (FMA vs LSU/atomic) and
//     overlap when co-resident.
// ---------------------------------------------------------------------------
#define BM 32
__global__ __launch_bounds__(128) void k_gemm_edge(const float* __restrict__ h,
                                                   const float* __restrict__ W,
                                                   const float* __restrict__ a,
                                                   const int*   __restrict__ ei,
                                                   int n, int ne, int ngemm) {
    __shared__ float hs[BM][IN_FEATS];        // 16 KB
    __shared__ float Ws[IN_FEATS][OUT_FEATS]; // 32 KB
    const int tid = threadIdx.x;

    if (blockIdx.x >= ngemm) {
        // ---------------- edge histogram part (128 thr, 4 edges/thr) -------
        // local dtype detect: int64 data has all-zero odd 32-bit words
        const int odd  = ei[2 * tid + 1];
        const int is64 = !__syncthreads_or(odd != 0);

        const int e0 = ((blockIdx.x - ngemm) * 128 + tid) * 4;
        if (e0 >= ne) return;
        const int cnt = (ne - e0 < 4) ? (ne - e0) : 4;

        int d[4];
        if (cnt == 4 && !is64 && ((ne & 3) == 0)) {
            int4 v = *(const int4*)&ei[ne + e0];
            d[0] = v.x; d[1] = v.y; d[2] = v.z; d[3] = v.w;
        } else if (cnt == 4 && is64 && ((ne & 1) == 0)) {
            int4 v0 = *(const int4*)&ei[2 * (ne + e0)];
            int4 v1 = *(const int4*)&ei[2 * (ne + e0) + 4];
            d[0] = v0.x; d[1] = v0.z; d[2] = v1.x; d[3] = v1.z;
        } else {
            for (int i = 0; i < 4; i++)
                d[i] = (i < cnt) ? (is64 ? ei[2 * (ne + e0 + i)] : ei[ne + e0 + i]) : 0;
        }
        #pragma unroll
        for (int i = 0; i < 4; i++) {
            if (i < cnt) {
                int dst = d[i];
                if ((unsigned)dst >= (unsigned)n) dst = 0;
                atomicAdd(g_cnt + dst, 1);
            }
        }
        return;
    }

    // ---------------- gemm part ------------------------------------------
    const int row0 = blockIdx.x * BM;

    {
        const float4* W4  = (const float4*)W;
        float4*       Ws4 = (float4*)&Ws[0][0];
        #pragma unroll
        for (int i = 0; i < 16; i++) Ws4[tid + i * 128] = W4[tid + i * 128];
    }
    {
        const float4* h4  = (const float4*)(h + (size_t)row0 * IN_FEATS);
        float4*       hs4 = (float4*)&hs[0][0];
        int nrow = n - row0; if (nrow > BM) nrow = BM;
        int nvec = nrow * (IN_FEATS / 4);
        #pragma unroll
        for (int i = 0; i < 8; i++) {
            int idx = tid + i * 128;
            float4 v = make_float4(0.f, 0.f, 0.f, 0.f);
            if (idx < nvec) v = h4[idx];
            hs4[idx] = v;
        }
    }
    __syncthreads();

    const int tx = tid & 31;   // lane: cols {tx, tx+32}
    const int ty = tid >> 5;   // warp: rows ty + 4*r

    float acc0[8], acc1[8];
    #pragma unroll
    for (int r = 0; r < 8; r++) { acc0[r] = 0.f; acc1[r] = 0.f; }

    #pragma unroll
    for (int k = 0; k < IN_FEATS; k += 4) {
        const float w00 = Ws[k + 0][tx], w01 = Ws[k + 0][tx + 32];
        const float w10 = Ws[k + 1][tx], w11 = Ws[k + 1][tx + 32];
        const float w20 = Ws[k + 2][tx], w21 = Ws[k + 2][tx + 32];
        const float w30 = Ws[k + 3][tx], w31 = Ws[k + 3][tx + 32];
        #pragma unroll
        for (int r = 0; r < 8; r++) {
            const float4 hv = *(const float4*)&hs[ty + 4 * r][k];
            acc0[r] = fmaf(hv.x, w00, acc0[r]);
            acc0[r] = fmaf(hv.y, w10, acc0[r]);
            acc0[r] = fmaf(hv.z, w20, acc0[r]);
            acc0[r] = fmaf(hv.w, w30, acc0[r]);
            acc1[r] = fmaf(hv.x, w01, acc1[r]);
            acc1[r] = fmaf(hv.y, w11, acc1[r]);
            acc1[r] = fmaf(hv.z, w21, acc1[r]);
            acc1[r] = fmaf(hv.w, w31, acc1[r]);
        }
    }

    const float a10 = a[tx], a11 = a[tx + 32];
    const float a20 = a[OUT_FEATS + tx], a21 = a[OUT_FEATS + tx + 32];

    int nrow = n - row0; if (nrow > BM) nrow = BM;
    #pragma unroll
    for (int r = 0; r < 8; r++) {
        const int row = ty + 4 * r;
        float p1 = acc0[r] * a10 + acc1[r] * a11;
        float p2 = acc0[r] * a20 + acc1[r] * a21;
        #pragma unroll
        for (int off = 16; off; off >>= 1) {
            p1 += __shfl_xor_sync(0xffffffffu, p1, off);
            p2 += __shfl_xor_sync(0xffffffffu, p2, off);
        }
        if (row < nrow) {
            float* dst = g_Wh + (size_t)(row0 + row) * OUT_FEATS;
            dst[tx]      = acc0[r];
            dst[tx + 32] = acc1[r];
            if (tx == 0) { g_s1[row0 + row] = p1; g_s2[row0 + row] = p2; }
        }
    }
}

// ---------------------------------------------------------------------------
// K2: fused exclusive scan (single kernel, decoupled publish).
//     Also re-zeroes g_cnt and g_bsum for the next graph replay.
//     All nb (<=49) blocks are co-resident, so polling cannot deadlock.
// ---------------------------------------------------------------------------
__global__ __launch_bounds__(256) void k_scan(int nb, int n) {
    const int b  = blockIdx.x;
    const int t  = threadIdx.x;
    const int i0 = b * SCAN_CHUNK + t * 4;

    int4 c = make_int4(0, 0, 0, 0);
    if (i0 + 3 < n) {
        c = *(const int4*)&g_cnt[i0];
    } else {
        if (i0 + 0 < n) c.x = g_cnt[i0 + 0];
        if (i0 + 1 < n) c.y = g_cnt[i0 + 1];
        if (i0 + 2 < n) c.z = g_cnt[i0 + 2];
        if (i0 + 3 < n) c.w = g_cnt[i0 + 3];
    }
    const int s = c.x + c.y + c.z + c.w;

    // block-wide inclusive scan of s
    const int lane = t & 31, wid = t >> 5;
    int v = s;
    #pragma unroll
    for (int off = 1; off < 32; off <<= 1) {
        int u = __shfl_up_sync(0xffffffffu, v, off);
        if (lane >= off) v += u;
    }
    __shared__ int wsum[8];
    if (lane == 31) wsum[wid] = v;
    __syncthreads();
    if (wid == 0 && lane < 8) {
        int w = wsum[lane];
        #pragma unroll
        for (int off = 1; off < 8; off <<= 1) {
            int u = __shfl_up_sync(0xffu, w, off);
            if (lane >= off) w += u;
        }
        wsum[lane] = w;
    }
    __syncthreads();
    const int incl = v + (wid ? wsum[wid - 1] : 0);
    const int excl = incl - s;

    // publish this block's total (+1 so 0 means "not ready")
    __shared__ int blk_total;
    if (t == 255) { blk_total = incl; atomicExch(&g_bsum[b], incl + 1); }

    // predecessor reduction (threads t < b poll & fetch)
    int pv = 0;
    if (t < b) {
        int x;
        do { x = atomicAdd(&g_bsum[t], 0); } while (x == 0);
        pv = x - 1;
    }
    #pragma unroll
    for (int off = 16; off; off >>= 1)
        pv += __shfl_xor_sync(0xffffffffu, pv, off);
    __shared__ int wred[8];
    if (lane == 0) wred[wid] = pv;
    __syncthreads();
    __shared__ int s_add;
    if (t == 0) {
        int a = 0;
        #pragma unroll
        for (int i = 0; i < 8; i++) a += wred[i];
        s_add = a;
    }
    __syncthreads();
    const int add = s_add;

    int4 p;
    p.x = excl + add;
    p.y = p.x + c.x;
    p.z = p.y + c.y;
    p.w = p.z + c.z;
    const int4 z = make_int4(0, 0, 0, 0);
    if (i0 + 3 < n) {
        *(int4*)&g_off[i0] = p;
        *(int4*)&g_cur[i0] = p;
        *(int4*)&g_cnt[i0] = z;          // reset for next replay
    } else {
        const int pv4[4] = {p.x, p.y, p.z, p.w};
        #pragma unroll
        for (int k = 0; k < 4; k++) {
            if (i0 + k < n) {
                g_off[i0 + k] = pv4[k];
                g_cur[i0 + k] = pv4[k];
                g_cnt[i0 + k] = 0;
            }
        }
    }
    if (b == nb - 1 && t == 255) g_off[n] = blk_total + add;

    // reset publish slot for next replay (after everyone has read it: only
    // successors read g_bsum[b], and every block with b' > b has already
    // fetched it before reaching here... not guaranteed — so defer the reset:
    // the LAST block (which no one polls) resets all slots.
    if (b == nb - 1) {
        __syncthreads();
        if (t < 256) g_bsum[t] = 0;      // safe: all other blocks have
                                          // already passed their polls
    }
}

// ---------------------------------------------------------------------------
// K3: fill CSR, 4 edges per thread, inline dtype detect, batched MLP loads.
//     slot = cur[dst]++;  cedge[slot] = {src, bits(exp(lrelu(s1+s2)))}
// ---------------------------------------------------------------------------
__global__ __launch_bounds__(256) void k_fill(const int* __restrict__ ei,
                                              int ne, int n) {
    const int t    = threadIdx.x;
    const int odd  = ei[2 * t + 1];
    const int is64 = !__syncthreads_or(odd != 0);

    const int e0 = (blockIdx.x * blockDim.x + t) * 4;
    if (e0 >= ne) return;
    const int cnt = (ne - e0 < 4) ? (ne - e0) : 4;

    int sr[4], ds[4];
    if (cnt == 4 && !is64 && ((ne & 3) == 0)) {
        int4 a = *(const int4*)&ei[e0];        // src
        int4 b = *(const int4*)&ei[ne + e0];   // dst
        sr[0] = a.x; sr[1] = a.y; sr[2] = a.z; sr[3] = a.w;
        ds[0] = b.x; ds[1] = b.y; ds[2] = b.z; ds[3] = b.w;
    } else if (cnt == 4 && is64 && ((ne & 1) == 0)) {
        int4 a0 = *(const int4*)&ei[2 * e0];
        int4 a1 = *(const int4*)&ei[2 * e0 + 4];
        int4 b0 = *(const int4*)&ei[2 * (ne + e0)];
        int4 b1 = *(const int4*)&ei[2 * (ne + e0) + 4];
        sr[0] = a0.x; sr[1] = a0.z; sr[2] = a1.x; sr[3] = a1.z;
        ds[0] = b0.x; ds[1] = b0.z; ds[2] = b1.x; ds[3] = b1.z;
    } else {
        for (int i = 0; i < 4; i++) {
            sr[i] = (i < cnt) ? (is64 ? ei[2 * (e0 + i)]      : ei[e0 + i])      : 0;
            ds[i] = (i < cnt) ? (is64 ? ei[2 * (ne + e0 + i)] : ei[ne + e0 + i]) : 0;
        }
    }
    #pragma unroll
    for (int i = 0; i < 4; i++) {
        if ((unsigned)sr[i] >= (unsigned)n) sr[i] = 0;
        if ((unsigned)ds[i] >= (unsigned)n) ds[i] = 0;
    }

    // batch the scattered score loads (8 independent L2 accesses in flight)
    float sv[4], dv[4];
    #pragma unroll
    for (int i = 0; i < 4; i++) {
        sv[i] = g_s1[sr[i]];
        dv[i] = g_s2[ds[i]];
    }
    #pragma unroll
    for (int i = 0; i < 4; i++) {
        if (i < cnt) {
            const float su = sv[i] + dv[i];
            const float lr = su > 0.0f ? su : ALPHA * su;
            const int slot = atomicAdd(g_cur + ds[i], 1);
            g_cedge[slot] = make_int2(sr[i], __float_as_int(__expf(lr)));
        }
    }
}

// ---------------------------------------------------------------------------
// K4: gather per dst node (16 threads/node, one float4 slice per lane),
//     4-wide unrolled edge loop for MLP.  out = elu(acc / dsum).
// ---------------------------------------------------------------------------
__global__ __launch_bounds__(256) void k_gather(float* __restrict__ out, int n) {
    const int gt   = blockIdx.x * blockDim.x + threadIdx.x;
    const int node = gt >> 4;
    const int lane = gt & 15;
    if (node >= n) return;

    const int beg = g_off[node];
    const int end = g_off[node + 1];

    const float4* __restrict__ Wh4 = (const float4*)g_Wh;
    const int2*   __restrict__ ced = g_cedge;
    float4 acc = make_float4(0.f, 0.f, 0.f, 0.f);
    float  dsum = 0.0f;

    int j = beg;
    for (; j + 4 <= end; j += 4) {
        const int2 c0 = ced[j],     c1 = ced[j + 1];
        const int2 c2 = ced[j + 2], c3 = ced[j + 3];
        const float4 v0 = Wh4[(size_t)c0.x * (OUT_FEATS / 4) + lane];
        const float4 v1 = Wh4[(size_t)c1.x * (OUT_FEATS / 4) + lane];
        const float4 v2 = Wh4[(size_t)c2.x * (OUT_FEATS / 4) + lane];
        const float4 v3 = Wh4[(size_t)c3.x * (OUT_FEATS / 4) + lane];
        const float w0 = __int_as_float(c0.y), w1 = __int_as_float(c1.y);
        const float w2 = __int_as_float(c2.y), w3 = __int_as_float(c3.y);

        acc.x = fmaf(w0, v0.x, acc.x); acc.y = fmaf(w0, v0.y, acc.y);
        acc.z = fmaf(w0, v0.z, acc.z); acc.w = fmaf(w0, v0.w, acc.w);
        acc.x = fmaf(w1, v1.x, acc.x); acc.y = fmaf(w1, v1.y, acc.y);
        acc.z = fmaf(w1, v1.z, acc.z); acc.w = fmaf(w1, v1.w, acc.w);
        acc.x = fmaf(w2, v2.x, acc.x); acc.y = fmaf(w2, v2.y, acc.y);
        acc.z = fmaf(w2, v2.z, acc.z); acc.w = fmaf(w2, v2.w, acc.w);
        acc.x = fmaf(w3, v3.x, acc.x); acc.y = fmaf(w3, v3.y, acc.y);
        acc.z = fmaf(w3, v3.z, acc.z); acc.w = fmaf(w3, v3.w, acc.w);
        dsum += (w0 + w1) + (w2 + w3);
    }
    for (; j < end; j++) {
        const int2 c = ced[j];
        const float w = __int_as_float(c.y);
        const float4 v = Wh4[(size_t)c.x * (OUT_FEATS / 4) + lane];
        acc.x = fmaf(w, v.x, acc.x);
        acc.y = fmaf(w, v.y, acc.y);
        acc.z = fmaf(w, v.z, acc.z);
        acc.w = fmaf(w, v.w, acc.w);
        dsum += w;
    }

    const float inv = (end > beg) ? (1.0f / dsum) : 0.0f;
    float4 r;
    r.x = acc.x * inv;  r.y = acc.y * inv;
    r.z = acc.z * inv;  r.w = acc.w * inv;
    r.x = r.x > 0.f ? r.x : expm1f(r.x);
    r.y = r.y > 0.f ? r.y : expm1f(r.y);
    r.z = r.z > 0.f ? r.z : expm1f(r.z);
    r.w = r.w > 0.f ? r.w : expm1f(r.w);

    ((float4*)out)[(size_t)node * (OUT_FEATS / 4) + lane] = r;
}

// ---------------------------------------------------------------------------
// Launcher.  Inputs identified by element count (robust to ordering).
// ---------------------------------------------------------------------------
extern "C" void kernel_launch(void* const* d_in, const int* in_sizes, int n_in,
                              void* d_out, int out_size) {
    const float* h  = nullptr;
    const int*   ei = nullptr;
    const float* W  = nullptr;
    const float* a  = nullptr;
    int n = N_NODES, ne = N_EDGES;

    for (int i = 0; i < n_in; i++) {
        const int sz = in_sizes[i];
        if (sz == IN_FEATS * OUT_FEATS)       W  = (const float*)d_in[i];
        else if (sz == 2 * OUT_FEATS)         a  = (const float*)d_in[i];
        else if (sz == 2 * N_EDGES)           { ei = (const int*)d_in[i]; ne = sz / 2; }
        else if (sz == 4 * N_EDGES)           { ei = (const int*)d_in[i]; ne = sz / 4; }
        else                                  { h  = (const float*)d_in[i]; n = sz / IN_FEATS; }
    }
    if (n > N_NODES)  n  = N_NODES;   // protect static scratch
    if (ne > N_EDGES) ne = N_EDGES;

    const int ngemm = (n + BM - 1) / BM;          // 1563
    const int nedge = (ne + 511) / 512;           // 1563 (128 thr x 4 edges)
    const int nb    = (n + SCAN_CHUNK - 1) / SCAN_CHUNK;   // 49 (<=256)

    k_gemm_edge<<<ngemm + nedge, 128>>>(h, W, a, ei, n, ne, ngemm);
    k_scan     <<<nb, 256>>>(nb, n);
    k_fill     <<<(ne / 4 + 255) / 256, 256>>>(ei, ne, n);
    k_gather   <<<(n * 16 + 255) / 256, 256>>>((float*)d_out, n);
}